// round 8
// baseline (speedup 1.0000x reference)
#include <cuda_runtime.h>
#include <cuda_fp16.h>
#include <cstdint>
#include <cstddef>

// ---------------- problem constants ----------------
#define T     4
#define WQ    75
#define WAY   5
#define SHOT  5
#define WS    (WAY*SHOT)        // 25
#define C     640
#define HW    100
#define MS    512               // padded rows per way (500 real + 12 zero)
#define MTOT  (WAY*MS)          // 2560
#define NQ    (WQ*HW)           // 7500
#define NPAD  7680              // 60 * 128
#define BM    128
#define BN    128
#define BKH   64                // K halves per chunk => 128B smem rows
#define KT    (C/BKH)           // 10
#define STAGES 3

#define MTILES (MTOT/BM)        // 20
#define NTILES (NPAD/BN)        // 60
#define TILES_TOTAL (T*MTILES*NTILES)   // 4800
#define NCTAS  296              // 2 per SM, persistent

#define A_BYTES    (BM*128)     // 16384
#define B_BYTES    (BN*128)     // 16384
#define STAGE_BYTES (A_BYTES + B_BYTES)              // 32768
#define SMEM_TOTAL  (STAGES*STAGE_BYTES)             // 98304

#define SWZ(o) ((o) ^ (((o) >> 3) & 0x70))
#define WAITG(n) asm volatile("cp.async.wait_group %0;" :: "n"(n))

__device__ __forceinline__ uint32_t smem_u32(const void* p) {
    uint32_t a;
    asm("{ .reg .u64 t; cvta.to.shared.u64 t, %1; cvt.u32.u64 %0, t; }" : "=r"(a) : "l"(p));
    return a;
}

// ---------------- scratch (__device__ globals) ----------------
__device__ __align__(256) __half g_S16[(size_t)T * MTOT * C];   // 13.1 MB
__device__ __align__(256) __half g_Q16[(size_t)T * NPAD * C];   // 39.3 MB
__device__ float g_meanS[T * WAY * C];
__device__ __align__(16) float g_colsum[T * WAY * NPAD];

// ---------------- kernel 1: fused prep — support means + pad S/Q + zero colsum ----------------
#define MEAN_BLOCKS 1600        // 12800 warps, one per (t,way,c)
#define NS_PAD  (T * WAY * (MS - SHOT*HW) * (C/2))    // 76800 half2
#define NQ_PAD  (T * (NPAD - NQ) * (C/2))             // 230400 half2
#define PAD_BLOCKS ((NS_PAD + NQ_PAD) / 256)          // 1200
#define ZERO_BLOCKS ((T * WAY * NPAD) / 4 / 256)      // 150
__global__ void prep_kernel(const float* __restrict__ sf, float* __restrict__ ms,
                            __half* __restrict__ S, __half* __restrict__ Q,
                            float* __restrict__ cs) {
    int b = blockIdx.x;
    int tid = threadIdx.x;
    if (b < MEAN_BLOCKS) {
        int wid  = (b * 256 + tid) >> 5;
        int lane = tid & 31;
        int c   = wid % C;
        int way = (wid / C) % WAY;
        int t   = wid / (C * WAY);
        float v = 0.f;
        #pragma unroll
        for (int sh = 0; sh < SHOT; sh++) {
            const float* p = sf + ((size_t)((t * WAY + way) * SHOT + sh) * C + c) * HW;
            v += p[lane] + p[lane + 32] + p[lane + 64];
            if (lane < 4) v += p[lane + 96];
        }
        #pragma unroll
        for (int o = 16; o; o >>= 1) v += __shfl_xor_sync(~0u, v, o);
        if (!lane) ms[wid] = v * (1.0f / (SHOT * HW));
    } else if (b < MEAN_BLOCKS + PAD_BLOCKS) {
        int i = (b - MEAN_BLOCKS) * 256 + tid;
        if (i < NS_PAD) {
            int cp = i % (C / 2);
            int r  = (i / (C / 2)) % (MS - SHOT * HW);
            int wy = (i / ((C / 2) * (MS - SHOT * HW))) % WAY;
            int t  = i / ((C / 2) * (MS - SHOT * HW) * WAY);
            ((__half2*)S)[((size_t)t * MTOT + wy * MS + SHOT * HW + r) * (C / 2) + cp] =
                __floats2half2_rn(0.f, 0.f);
        } else {
            int j = i - NS_PAD;
            int cp = j % (C / 2);
            int r  = (j / (C / 2)) % (NPAD - NQ);
            int t  = j / ((C / 2) * (NPAD - NQ));
            ((__half2*)Q)[((size_t)t * NPAD + NQ + r) * (C / 2) + cp] =
                __floats2half2_rn(0.f, 0.f);
        }
    } else {
        int i = (b - MEAN_BLOCKS - PAD_BLOCKS) * 256 + tid;
        ((float4*)cs)[i] = make_float4(0.f, 0.f, 0.f, 0.f);
    }
}

// ---------------- kernel 2: coalesced center+transpose support -> fp16 K-major ----------------
__global__ void __launch_bounds__(256) center_s_kernel(const float* __restrict__ sf,
                                                       const float* __restrict__ ms,
                                                       __half* __restrict__ out) {
    __shared__ float tile[64 * 101];
    int b  = blockIdx.x;
    int cc = b % (C / 64);
    int ws = (b / (C / 64)) % WS;
    int t  = b / ((C / 64) * WS);
    int way = ws / SHOT, sh = ws % SHOT;
    int c0 = cc * 64;
    const float* src = sf + ((size_t)(t * WS + ws) * C + c0) * HW;
    int tid = threadIdx.x;
    #pragma unroll
    for (int i = 0; i < 25; i++) {
        int idx = tid + i * 256;
        tile[(idx / 100) * 101 + (idx % 100)] = src[idx];
    }
    __syncthreads();
    const float* mrow = ms + (t * WAY + way) * C + c0;
    __half2* dst = (__half2*)(out + ((size_t)t * MTOT + way * MS + sh * HW) * C + c0);
    for (int i = tid; i < 32 * HW; i += 256) {
        int n = i / 32, cp = i % 32;
        float v0 = tile[(cp * 2) * 101 + n] - mrow[cp * 2];
        float v1 = tile[(cp * 2 + 1) * 101 + n] - mrow[cp * 2 + 1];
        dst[(size_t)n * (C / 2) + cp] = __floats2half2_rn(v0, v1);
    }
}

// ---------------- kernel 3: coalesced center(fused mean)+transpose query -> fp16 ----------------
__global__ void __launch_bounds__(256) center_q_kernel(const float* __restrict__ qf,
                                                       __half* __restrict__ out) {
    __shared__ float tile[64 * 101];
    __shared__ float mean[64];
    int b  = blockIdx.x;
    int cc = b % (C / 64);
    int q  = (b / (C / 64)) % WQ;
    int t  = b / ((C / 64) * WQ);
    int c0 = cc * 64;
    const float* src = qf + ((size_t)(t * WQ + q) * C + c0) * HW;
    int tid = threadIdx.x, warp = tid >> 5, lane = tid & 31;
    #pragma unroll
    for (int i = 0; i < 25; i++) {
        int idx = tid + i * 256;
        tile[(idx / 100) * 101 + (idx % 100)] = src[idx];
    }
    __syncthreads();
    #pragma unroll
    for (int r = warp; r < 64; r += 8) {
        const float* row = &tile[r * 101];
        float v = row[lane] + row[lane + 32] + row[lane + 64];
        if (lane < 4) v += row[lane + 96];
        #pragma unroll
        for (int o = 16; o; o >>= 1) v += __shfl_xor_sync(~0u, v, o);
        if (!lane) mean[r] = v * (1.0f / HW);
    }
    __syncthreads();
    __half2* dst = (__half2*)(out + ((size_t)t * NPAD + q * HW) * C + c0);
    for (int i = tid; i < 32 * HW; i += 256) {
        int n = i / 32, cp = i % 32;
        float v0 = tile[(cp * 2) * 101 + n] - mean[cp * 2];
        float v1 = tile[(cp * 2 + 1) * 101 + n] - mean[cp * 2 + 1];
        dst[(size_t)n * (C / 2) + cp] = __floats2half2_rn(v0, v1);
    }
}

// ---------------- kernel 4: PERSISTENT fp16 HMMA GEMM + fused column sum-of-squares ----------------
// 296 CTAs (2/SM), 128 threads (4 warps 2x2, warp tile 64x64). The 3-stage cp.async
// ring runs continuously ACROSS tiles: during the last chunks of tile i we prefetch
// chunk 0/1 of tile i+1 — no pipeline refill per tile.
__global__ void __launch_bounds__(128, 2) gemm_hmma_kernel(const __half* __restrict__ A,
                                                           const __half* __restrict__ B,
                                                           float* __restrict__ colsum) {
    extern __shared__ char smem[];
    const uint32_t sb = smem_u32(smem);

    const int tid  = threadIdx.x;
    const int warp = tid >> 5, lane = tid & 31;
    const int wm = warp & 1;          // 0..1 : 64-row half (M)
    const int wn = warp >> 1;         // 0..1 : 64-col half (N)
    const int gid = lane >> 2, tig = lane & 3;

    const int cta = blockIdx.x;
    const int ntiles = (TILES_TOTAL - cta + NCTAS - 1) / NCTAS;

    const int arow = lane & 15;
    const int akof = (lane >> 4) * 16;
    const int brow = ((lane >> 4) << 3) | (lane & 7);
    const int bkof = ((lane >> 3) & 1) * 16;

    auto tile_ptrs = [&](int tile, const __half*& pA, const __half*& pB,
                         int& tt, int& mm) {
        int n = tile % NTILES;
        int m = (tile / NTILES) % MTILES;
        int t = tile / (NTILES * MTILES);
        tt = t; mm = m;
        pA = A + ((size_t)t * MTOT + m * BM) * C;
        pB = B + ((size_t)t * NPAD + n * BN) * C;
    };

    auto issue = [&](const __half* pA, const __half* pB, int s, int k0) {
        const uint32_t sA = sb + s * STAGE_BYTES;
        const uint32_t sB = sA + A_BYTES;
        #pragma unroll
        for (int it = 0; it < 8; it++) {               // A: 1024 x 16B
            int i   = tid + it * 128;
            int row = i >> 3, ch = i & 7;
            uint32_t dst = sA + SWZ(row * 128 + ch * 16);
            const __half* src = pA + (size_t)row * C + k0 + ch * 8;
            asm volatile("cp.async.cg.shared.global [%0], [%1], 16;" :: "r"(dst), "l"(src));
        }
        #pragma unroll
        for (int it = 0; it < 8; it++) {               // B: 1024 x 16B
            int i   = tid + it * 128;
            int row = i >> 3, ch = i & 7;
            uint32_t dst = sB + SWZ(row * 128 + ch * 16);
            const __half* src = pB + (size_t)row * C + k0 + ch * 8;
            asm volatile("cp.async.cg.shared.global [%0], [%1], 16;" :: "r"(dst), "l"(src));
        }
        asm volatile("cp.async.commit_group;");
    };

    float acc[4][8][4];
    #pragma unroll
    for (int mi = 0; mi < 4; mi++)
        #pragma unroll
        for (int ni = 0; ni < 8; ni++)
            #pragma unroll
            for (int r = 0; r < 4; r++) acc[mi][ni][r] = 0.f;

    // current/next tile pointers
    const __half *cA, *cB, *nA = nullptr, *nB = nullptr;
    int curT, curM, nxT, nxM;
    tile_ptrs(cta, cA, cB, curT, curM);

    // prologue: fill stages 0,1 with chunks 0,1 of tile 0
    issue(cA, cB, 0, 0);
    issue(cA, cB, 1, BKH);

    int csg = 0;   // compute stage (g % 3)
    int isg = 2;   // issue stage ((g+2) % 3)

    for (int ti = 0; ti < ntiles; ti++) {
        const bool have_next = (ti + 1 < ntiles);
        if (have_next) tile_ptrs(cta + (ti + 1) * NCTAS, nA, nB, nxT, nxM);

        for (int kc = 0; kc < KT; kc++) {
            const bool last = (!have_next) && (kc == KT - 1);
            if (last) { WAITG(0); } else { WAITG(1); }
            __syncthreads();

            // issue chunk (g+2): current tile kc+2, or next tile kc-8
            if (kc + 2 < KT) {
                issue(cA, cB, isg, (kc + 2) * BKH);
            } else if (have_next) {
                issue(nA, nB, isg, (kc + 2 - KT) * BKH);
            }

            const uint32_t sA = sb + csg * STAGE_BYTES;
            const uint32_t sB = sA + A_BYTES;

            #pragma unroll
            for (int ks = 0; ks < 4; ks++) {
                const int kb = ks * 32;
                uint32_t a[4][4], b[8][2];
                #pragma unroll
                for (int mi = 0; mi < 4; mi++) {
                    uint32_t addr = sA + SWZ((wm * 64 + mi * 16 + arow) * 128 + kb + akof);
                    asm volatile("ldmatrix.sync.aligned.m8n8.x4.shared.b16 {%0,%1,%2,%3}, [%4];"
                                 : "=r"(a[mi][0]), "=r"(a[mi][1]), "=r"(a[mi][2]), "=r"(a[mi][3])
                                 : "r"(addr));
                }
                #pragma unroll
                for (int nj = 0; nj < 4; nj++) {
                    uint32_t addr = sB + SWZ((wn * 64 + nj * 16 + brow) * 128 + kb + bkof);
                    asm volatile("ldmatrix.sync.aligned.m8n8.x4.shared.b16 {%0,%1,%2,%3}, [%4];"
                                 : "=r"(b[nj*2][0]), "=r"(b[nj*2][1]),
                                   "=r"(b[nj*2+1][0]), "=r"(b[nj*2+1][1])
                                 : "r"(addr));
                }
                #pragma unroll
                for (int mi = 0; mi < 4; mi++)
                    #pragma unroll
                    for (int ni = 0; ni < 8; ni++) {
                        asm volatile(
                            "mma.sync.aligned.m16n8k16.row.col.f32.f16.f16.f32 "
                            "{%0,%1,%2,%3}, {%4,%5,%6,%7}, {%8,%9}, {%0,%1,%2,%3};"
                            : "+f"(acc[mi][ni][0]), "+f"(acc[mi][ni][1]),
                              "+f"(acc[mi][ni][2]), "+f"(acc[mi][ni][3])
                            : "r"(a[mi][0]), "r"(a[mi][1]), "r"(a[mi][2]), "r"(a[mi][3]),
                              "r"(b[ni][0]), "r"(b[ni][1]));
                    }
            }
            if (++csg == STAGES) csg = 0;
            if (++isg == STAGES) isg = 0;
        }

        // ---- per-tile epilogue: column sum-of-squares (registers only, overlaps loads) ----
        {
            int tile = cta + ti * NCTAS;
            int n = tile % NTILES;
            const int way = (curM * BM) / MS;
            float* cs = colsum + ((size_t)curT * WAY + way) * NPAD + n * BN;
            #pragma unroll
            for (int ni = 0; ni < 8; ni++) {
                float v0 = 0.f, v1 = 0.f;
                #pragma unroll
                for (int mi = 0; mi < 4; mi++) {
                    v0 += acc[mi][ni][0] * acc[mi][ni][0] + acc[mi][ni][2] * acc[mi][ni][2];
                    v1 += acc[mi][ni][1] * acc[mi][ni][1] + acc[mi][ni][3] * acc[mi][ni][3];
                }
                #pragma unroll
                for (int o = 4; o < 32; o <<= 1) {
                    v0 += __shfl_xor_sync(~0u, v0, o);
                    v1 += __shfl_xor_sync(~0u, v1, o);
                }
                if (gid == 0) {
                    int col = wn * 64 + ni * 8 + tig * 2;
                    atomicAdd(&cs[col], v0);
                    atomicAdd(&cs[col + 1], v1);
                }
            }
            #pragma unroll
            for (int mi = 0; mi < 4; mi++)
                #pragma unroll
                for (int ni = 0; ni < 8; ni++)
                    #pragma unroll
                    for (int r = 0; r < 4; r++) acc[mi][ni][r] = 0.f;
        }

        cA = nA; cB = nB; curT = nxT; curM = nxM;
    }
}

// ---------------- kernel 5: /99, LeakyReLU(0.2), conv1d(k=stride=100), +bias ----------------
__global__ void final_kernel(const float* __restrict__ colsum, const float* __restrict__ cw,
                             const float* __restrict__ cb, float* __restrict__ out) {
    int wid  = (blockIdx.x * blockDim.x + threadIdx.x) >> 5;
    int lane = threadIdx.x & 31;
    if (wid >= T * WQ * WAY) return;
    int w = wid % WAY;
    int q = (wid / WAY) % WQ;
    int t = wid / (WAY * WQ);
    const float* cs = colsum + ((size_t)t * WAY + w) * NPAD + q * HW;
    float v = 0.f;
    #pragma unroll
    for (int i = 0; i < 4; i++) {
        int n = lane + 32 * i;
        if (n < HW) {
            float x = cs[n] * (1.0f / 99.0f);
            x = (x >= 0.f) ? x : 0.2f * x;
            v += x * cw[n];
        }
    }
    #pragma unroll
    for (int o = 16; o; o >>= 1) v += __shfl_xor_sync(~0u, v, o);
    if (!lane) out[wid] = v + cb[0];
}

// ---------------- launch ----------------
extern "C" void kernel_launch(void* const* d_in, const int* in_sizes, int n_in,
                              void* d_out, int out_size) {
    const float* qf = (const float*)d_in[0];
    const float* sf = (const float*)d_in[1];
    const float* cw = (const float*)d_in[2];
    const float* cb = (const float*)d_in[3];
    float* out = (float*)d_out;

    __half *dS, *dQ;
    float *dMS, *dCS;
    cudaGetSymbolAddress((void**)&dS,  g_S16);
    cudaGetSymbolAddress((void**)&dQ,  g_Q16);
    cudaGetSymbolAddress((void**)&dMS, g_meanS);
    cudaGetSymbolAddress((void**)&dCS, g_colsum);

    // 1) fused prep: support means + pads + zero colsum
    prep_kernel<<<MEAN_BLOCKS + PAD_BLOCKS + ZERO_BLOCKS, 256>>>(sf, dMS, dS, dQ, dCS);
    // 2) center+transpose S -> fp16
    center_s_kernel<<<T * WS * (C / 64), 256>>>(sf, dMS, dS);
    // 3) center(fused mean)+transpose Q -> fp16
    center_q_kernel<<<T * WQ * (C / 64), 256>>>(qf, dQ);
    // 4) persistent GEMM + fused sum-of-squares   (4th launch -> ncu capture slot)
    cudaFuncSetAttribute(gemm_hmma_kernel, cudaFuncAttributeMaxDynamicSharedMemorySize, SMEM_TOTAL);
    gemm_hmma_kernel<<<NCTAS, 128, SMEM_TOTAL>>>(dS, dQ, dCS);
    // 5) final score
    int warps = T * WQ * WAY;
    final_kernel<<<(warps * 32 + 255) / 256, 256>>>(dCS, cw, cb, out);
}

// round 9
// speedup vs baseline: 1.0376x; 1.0376x over previous
#include <cuda_runtime.h>
#include <cuda_fp16.h>
#include <cstdint>
#include <cstddef>

// ---------------- problem constants ----------------
#define T     4
#define WQ    75
#define WAY   5
#define SHOT  5
#define WS    (WAY*SHOT)        // 25
#define C     640
#define HW    100
#define MS    512               // padded rows per way (500 real + 12 zero)
#define MTOT  (WAY*MS)          // 2560
#define NQ    (WQ*HW)           // 7500
#define NPAD  7680              // 120 * 64
#define BM    128
#define BN    64
#define BKH   64                // K halves per chunk => 128B smem rows
#define KT    (C/BKH)           // 10
#define STAGES 3

#define A_BYTES    (BM*128)     // 16384
#define B_BYTES    (BN*128)     // 8192
#define STAGE_BYTES (A_BYTES + B_BYTES)              // 24576
#define SMEM_TOTAL  (STAGES*STAGE_BYTES)             // 73728

#define SWZ(o) ((o) ^ (((o) >> 3) & 0x70))
#define WAITG(n) asm volatile("cp.async.wait_group %0;" :: "n"(n))

__device__ __forceinline__ uint32_t smem_u32(const void* p) {
    uint32_t a;
    asm("{ .reg .u64 t; cvta.to.shared.u64 t, %1; cvt.u32.u64 %0, t; }" : "=r"(a) : "l"(p));
    return a;
}

// ---------------- scratch (__device__ globals) ----------------
__device__ __align__(256) __half g_S16[(size_t)T * MTOT * C];   // 13.1 MB
__device__ __align__(256) __half g_Q16[(size_t)T * NPAD * C];   // 39.3 MB
__device__ float g_meanS[T * WAY * C];
__device__ __align__(16) float g_colsum[T * WAY * NPAD];

// ---------------- kernel 1: fused prep — support means + pad S/Q + zero colsum ----------------
#define MEAN_BLOCKS 1600        // 12800 warps, one per (t,way,c)
#define NS_PAD  (T * WAY * (MS - SHOT*HW) * (C/2))    // 76800 half2
#define NQ_PAD  (T * (NPAD - NQ) * (C/2))             // 230400 half2
#define PAD_BLOCKS ((NS_PAD + NQ_PAD) / 256)          // 1200
#define ZERO_BLOCKS ((T * WAY * NPAD) / 4 / 256)      // 150
__global__ void prep_kernel(const float* __restrict__ sf, float* __restrict__ ms,
                            __half* __restrict__ S, __half* __restrict__ Q,
                            float* __restrict__ cs) {
    int b = blockIdx.x;
    int tid = threadIdx.x;
    if (b < MEAN_BLOCKS) {
        int wid  = (b * 256 + tid) >> 5;
        int lane = tid & 31;
        int c   = wid % C;
        int way = (wid / C) % WAY;
        int t   = wid / (C * WAY);
        float v = 0.f;
        #pragma unroll
        for (int sh = 0; sh < SHOT; sh++) {
            const float* p = sf + ((size_t)((t * WAY + way) * SHOT + sh) * C + c) * HW;
            v += p[lane] + p[lane + 32] + p[lane + 64];
            if (lane < 4) v += p[lane + 96];
        }
        #pragma unroll
        for (int o = 16; o; o >>= 1) v += __shfl_xor_sync(~0u, v, o);
        if (!lane) ms[wid] = v * (1.0f / (SHOT * HW));
    } else if (b < MEAN_BLOCKS + PAD_BLOCKS) {
        int i = (b - MEAN_BLOCKS) * 256 + tid;
        if (i < NS_PAD) {
            int cp = i % (C / 2);
            int r  = (i / (C / 2)) % (MS - SHOT * HW);
            int wy = (i / ((C / 2) * (MS - SHOT * HW))) % WAY;
            int t  = i / ((C / 2) * (MS - SHOT * HW) * WAY);
            ((__half2*)S)[((size_t)t * MTOT + wy * MS + SHOT * HW + r) * (C / 2) + cp] =
                __floats2half2_rn(0.f, 0.f);
        } else {
            int j = i - NS_PAD;
            int cp = j % (C / 2);
            int r  = (j / (C / 2)) % (NPAD - NQ);
            int t  = j / ((C / 2) * (NPAD - NQ));
            ((__half2*)Q)[((size_t)t * NPAD + NQ + r) * (C / 2) + cp] =
                __floats2half2_rn(0.f, 0.f);
        }
    } else {
        int i = (b - MEAN_BLOCKS - PAD_BLOCKS) * 256 + tid;
        ((float4*)cs)[i] = make_float4(0.f, 0.f, 0.f, 0.f);
    }
}

// ---------------- kernel 2: coalesced center+transpose support -> fp16 K-major ----------------
__global__ void __launch_bounds__(256) center_s_kernel(const float* __restrict__ sf,
                                                       const float* __restrict__ ms,
                                                       __half* __restrict__ out) {
    __shared__ float tile[64 * 101];
    int b  = blockIdx.x;
    int cc = b % (C / 64);
    int ws = (b / (C / 64)) % WS;
    int t  = b / ((C / 64) * WS);
    int way = ws / SHOT, sh = ws % SHOT;
    int c0 = cc * 64;
    const float* src = sf + ((size_t)(t * WS + ws) * C + c0) * HW;
    int tid = threadIdx.x;
    #pragma unroll
    for (int i = 0; i < 25; i++) {
        int idx = tid + i * 256;
        tile[(idx / 100) * 101 + (idx % 100)] = src[idx];
    }
    __syncthreads();
    const float* mrow = ms + (t * WAY + way) * C + c0;
    __half2* dst = (__half2*)(out + ((size_t)t * MTOT + way * MS + sh * HW) * C + c0);
    for (int i = tid; i < 32 * HW; i += 256) {
        int n = i / 32, cp = i % 32;
        float v0 = tile[(cp * 2) * 101 + n] - mrow[cp * 2];
        float v1 = tile[(cp * 2 + 1) * 101 + n] - mrow[cp * 2 + 1];
        dst[(size_t)n * (C / 2) + cp] = __floats2half2_rn(v0, v1);
    }
}

// ---------------- kernel 3: coalesced center(fused mean)+transpose query -> fp16 ----------------
__global__ void __launch_bounds__(256) center_q_kernel(const float* __restrict__ qf,
                                                       __half* __restrict__ out) {
    __shared__ float tile[64 * 101];
    __shared__ float mean[64];
    int b  = blockIdx.x;
    int cc = b % (C / 64);
    int q  = (b / (C / 64)) % WQ;
    int t  = b / ((C / 64) * WQ);
    int c0 = cc * 64;
    const float* src = qf + ((size_t)(t * WQ + q) * C + c0) * HW;
    int tid = threadIdx.x, warp = tid >> 5, lane = tid & 31;
    #pragma unroll
    for (int i = 0; i < 25; i++) {
        int idx = tid + i * 256;
        tile[(idx / 100) * 101 + (idx % 100)] = src[idx];
    }
    __syncthreads();
    #pragma unroll
    for (int r = warp; r < 64; r += 8) {
        const float* row = &tile[r * 101];
        float v = row[lane] + row[lane + 32] + row[lane + 64];
        if (lane < 4) v += row[lane + 96];
        #pragma unroll
        for (int o = 16; o; o >>= 1) v += __shfl_xor_sync(~0u, v, o);
        if (!lane) mean[r] = v * (1.0f / HW);
    }
    __syncthreads();
    __half2* dst = (__half2*)(out + ((size_t)t * NPAD + q * HW) * C + c0);
    for (int i = tid; i < 32 * HW; i += 256) {
        int n = i / 32, cp = i % 32;
        float v0 = tile[(cp * 2) * 101 + n] - mean[cp * 2];
        float v1 = tile[(cp * 2 + 1) * 101 + n] - mean[cp * 2 + 1];
        dst[(size_t)n * (C / 2) + cp] = __floats2half2_rn(v0, v1);
    }
}

// ---------------- kernel 4: fp16 HMMA GEMM (128x64 CTA) + fused column sum-of-squares ----------------
// 128 threads (4 warps 2x2), warp tile 64x32. 3 CTAs/SM (72KB smem, <=170 regs)
// -> 3 warps/SMSP for better tensor-pipe gap coverage.
// 3 stages: WAITG -> sync -> issue(kc+2) -> compute.
__global__ void __launch_bounds__(128, 3) gemm_hmma_kernel(const __half* __restrict__ A,
                                                           const __half* __restrict__ B,
                                                           float* __restrict__ colsum) {
    extern __shared__ char smem[];
    const uint32_t sb = smem_u32(smem);

    const int tid  = threadIdx.x;
    const int warp = tid >> 5, lane = tid & 31;
    const int wm = warp & 1;          // 0..1 : 64-row half (M)
    const int wn = warp >> 1;         // 0..1 : 32-col half (N)
    const int gid = lane >> 2, tig = lane & 3;

    const int t  = blockIdx.z;
    const int m0 = blockIdx.y * BM;
    const int n0 = blockIdx.x * BN;
    const __half* Ap = A + ((size_t)t * MTOT + m0) * C;
    const __half* Bp = B + ((size_t)t * NPAD + n0) * C;

    const int arow = lane & 15;
    const int akof = (lane >> 4) * 16;
    const int brow = ((lane >> 4) << 3) | (lane & 7);
    const int bkof = ((lane >> 3) & 1) * 16;

    auto issue = [&](int kc) {
        const int s  = kc % STAGES;
        const int k0 = kc * BKH;
        const uint32_t sA = sb + s * STAGE_BYTES;
        const uint32_t sB = sA + A_BYTES;
        #pragma unroll
        for (int it = 0; it < 8; it++) {               // A: 1024 x 16B
            int i   = tid + it * 128;
            int row = i >> 3, ch = i & 7;
            uint32_t dst = sA + SWZ(row * 128 + ch * 16);
            const __half* src = Ap + (size_t)row * C + k0 + ch * 8;
            asm volatile("cp.async.cg.shared.global [%0], [%1], 16;" :: "r"(dst), "l"(src));
        }
        #pragma unroll
        for (int it = 0; it < 4; it++) {               // B: 512 x 16B
            int i   = tid + it * 128;
            int row = i >> 3, ch = i & 7;
            uint32_t dst = sB + SWZ(row * 128 + ch * 16);
            const __half* src = Bp + (size_t)row * C + k0 + ch * 8;
            asm volatile("cp.async.cg.shared.global [%0], [%1], 16;" :: "r"(dst), "l"(src));
        }
        asm volatile("cp.async.commit_group;");
    };

    float acc[4][4][4];
    #pragma unroll
    for (int mi = 0; mi < 4; mi++)
        #pragma unroll
        for (int ni = 0; ni < 4; ni++)
            #pragma unroll
            for (int r = 0; r < 4; r++) acc[mi][ni][r] = 0.f;

    issue(0); issue(1);

    for (int kc = 0; kc < KT; kc++) {
        if (kc < KT - 1) { WAITG(1); }   // stage kc complete (1 newer group may pend)
        else             { WAITG(0); }
        __syncthreads();                 // data visible + all warps done reading stage (kc-1)%3
        if (kc + 2 < KT) issue(kc + 2);  // writes stage (kc-1)%3 — safe after the sync

        const uint32_t sA = sb + (kc % STAGES) * STAGE_BYTES;
        const uint32_t sB = sA + A_BYTES;

        #pragma unroll
        for (int ks = 0; ks < 4; ks++) {
            const int kb = ks * 32;
            uint32_t a[4][4], b[4][2];
            #pragma unroll
            for (int mi = 0; mi < 4; mi++) {
                uint32_t addr = sA + SWZ((wm * 64 + mi * 16 + arow) * 128 + kb + akof);
                asm volatile("ldmatrix.sync.aligned.m8n8.x4.shared.b16 {%0,%1,%2,%3}, [%4];"
                             : "=r"(a[mi][0]), "=r"(a[mi][1]), "=r"(a[mi][2]), "=r"(a[mi][3])
                             : "r"(addr));
            }
            #pragma unroll
            for (int nj = 0; nj < 2; nj++) {           // 32 cols = 2 x (16-row x4)
                uint32_t addr = sB + SWZ((wn * 32 + nj * 16 + brow) * 128 + kb + bkof);
                asm volatile("ldmatrix.sync.aligned.m8n8.x4.shared.b16 {%0,%1,%2,%3}, [%4];"
                             : "=r"(b[nj*2][0]), "=r"(b[nj*2][1]),
                               "=r"(b[nj*2+1][0]), "=r"(b[nj*2+1][1])
                             : "r"(addr));
            }
            #pragma unroll
            for (int mi = 0; mi < 4; mi++)
                #pragma unroll
                for (int ni = 0; ni < 4; ni++) {
                    asm volatile(
                        "mma.sync.aligned.m16n8k16.row.col.f32.f16.f16.f32 "
                        "{%0,%1,%2,%3}, {%4,%5,%6,%7}, {%8,%9}, {%0,%1,%2,%3};"
                        : "+f"(acc[mi][ni][0]), "+f"(acc[mi][ni][1]),
                          "+f"(acc[mi][ni][2]), "+f"(acc[mi][ni][3])
                        : "r"(a[mi][0]), "r"(a[mi][1]), "r"(a[mi][2]), "r"(a[mi][3]),
                          "r"(b[ni][0]), "r"(b[ni][1]));
                }
        }
    }

    // -------- fused epilogue: column sum of squares over this CTA's 128 rows --------
    const int way = m0 / MS;
    float* cs = colsum + ((size_t)t * WAY + way) * NPAD + n0;
    #pragma unroll
    for (int ni = 0; ni < 4; ni++) {
        float v0 = 0.f, v1 = 0.f;
        #pragma unroll
        for (int mi = 0; mi < 4; mi++) {
            v0 += acc[mi][ni][0] * acc[mi][ni][0] + acc[mi][ni][2] * acc[mi][ni][2];
            v1 += acc[mi][ni][1] * acc[mi][ni][1] + acc[mi][ni][3] * acc[mi][ni][3];
        }
        #pragma unroll
        for (int o = 4; o < 32; o <<= 1) {
            v0 += __shfl_xor_sync(~0u, v0, o);
            v1 += __shfl_xor_sync(~0u, v1, o);
        }
        if (gid == 0) {
            int col = wn * 32 + ni * 8 + tig * 2;
            atomicAdd(&cs[col], v0);       // two warps (wm=0/1) accumulate same cols
            atomicAdd(&cs[col + 1], v1);
        }
    }
}

// ---------------- kernel 5: /99, LeakyReLU(0.2), conv1d(k=stride=100), +bias ----------------
__global__ void final_kernel(const float* __restrict__ colsum, const float* __restrict__ cw,
                             const float* __restrict__ cb, float* __restrict__ out) {
    int wid  = (blockIdx.x * blockDim.x + threadIdx.x) >> 5;
    int lane = threadIdx.x & 31;
    if (wid >= T * WQ * WAY) return;
    int w = wid % WAY;
    int q = (wid / WAY) % WQ;
    int t = wid / (WAY * WQ);
    const float* cs = colsum + ((size_t)t * WAY + w) * NPAD + q * HW;
    float v = 0.f;
    #pragma unroll
    for (int i = 0; i < 4; i++) {
        int n = lane + 32 * i;
        if (n < HW) {
            float x = cs[n] * (1.0f / 99.0f);
            x = (x >= 0.f) ? x : 0.2f * x;
            v += x * cw[n];
        }
    }
    #pragma unroll
    for (int o = 16; o; o >>= 1) v += __shfl_xor_sync(~0u, v, o);
    if (!lane) out[wid] = v + cb[0];
}

// ---------------- launch ----------------
extern "C" void kernel_launch(void* const* d_in, const int* in_sizes, int n_in,
                              void* d_out, int out_size) {
    const float* qf = (const float*)d_in[0];
    const float* sf = (const float*)d_in[1];
    const float* cw = (const float*)d_in[2];
    const float* cb = (const float*)d_in[3];
    float* out = (float*)d_out;

    __half *dS, *dQ;
    float *dMS, *dCS;
    cudaGetSymbolAddress((void**)&dS,  g_S16);
    cudaGetSymbolAddress((void**)&dQ,  g_Q16);
    cudaGetSymbolAddress((void**)&dMS, g_meanS);
    cudaGetSymbolAddress((void**)&dCS, g_colsum);

    // 1) fused prep: support means + pads + zero colsum
    prep_kernel<<<MEAN_BLOCKS + PAD_BLOCKS + ZERO_BLOCKS, 256>>>(sf, dMS, dS, dQ, dCS);
    // 2) center+transpose S -> fp16
    center_s_kernel<<<T * WS * (C / 64), 256>>>(sf, dMS, dS);
    // 3) center(fused mean)+transpose Q -> fp16
    center_q_kernel<<<T * WQ * (C / 64), 256>>>(qf, dQ);
    // 4) GEMM + fused sum-of-squares   (4th launch -> ncu capture slot)
    cudaFuncSetAttribute(gemm_hmma_kernel, cudaFuncAttributeMaxDynamicSharedMemorySize, SMEM_TOTAL);
    dim3 grid(NPAD / BN, MTOT / BM, T);   // (120, 20, 4)
    gemm_hmma_kernel<<<grid, 128, SMEM_TOTAL>>>(dS, dQ, dCS);
    // 5) final score
    int warps = T * WQ * WAY;
    final_kernel<<<(warps * 32 + 255) / 256, 256>>>(dCS, cw, cb, out);
}

// round 10
// speedup vs baseline: 1.0943x; 1.0546x over previous
#include <cuda_runtime.h>
#include <cuda_fp16.h>
#include <cstdint>
#include <cstddef>

// ---------------- problem constants ----------------
#define T     4
#define WQ    75
#define WAY   5
#define SHOT  5
#define WS    (WAY*SHOT)        // 25
#define C     640
#define HW    100
#define MS    512               // padded rows per way (500 real + 12 zero)
#define MTOT  (WAY*MS)          // 2560
#define NQ    (WQ*HW)           // 7500
#define NPAD  7552              // 59 * 128  -> grid 4720 = 15*296 + 280 (good tail)
#define BM    128
#define BN    128
#define BKH   64                // K halves per chunk => 128B smem rows
#define KT    (C/BKH)           // 10
#define STAGES 3

#define A_BYTES    (BM*128)     // 16384
#define B_BYTES    (BN*128)     // 16384
#define STAGE_BYTES (A_BYTES + B_BYTES)              // 32768
#define SMEM_TOTAL  (STAGES*STAGE_BYTES)             // 98304

#define SWZ(o) ((o) ^ (((o) >> 3) & 0x70))
#define WAITG(n) asm volatile("cp.async.wait_group %0;" :: "n"(n))

__device__ __forceinline__ uint32_t smem_u32(const void* p) {
    uint32_t a;
    asm("{ .reg .u64 t; cvta.to.shared.u64 t, %1; cvt.u32.u64 %0, t; }" : "=r"(a) : "l"(p));
    return a;
}

// ---------------- scratch (__device__ globals) ----------------
__device__ __align__(256) __half g_S16[(size_t)T * MTOT * C];   // 13.1 MB
__device__ __align__(256) __half g_Q16[(size_t)T * NPAD * C];   // 38.7 MB
__device__ float g_meanS[T * WAY * C];
__device__ __align__(16) float g_colsum[T * WAY * NPAD];

// ---------------- kernel 1: support channel means ----------------
__global__ void means_s_kernel(const float* __restrict__ sf, float* __restrict__ ms) {
    int wid  = (blockIdx.x * blockDim.x + threadIdx.x) >> 5;
    int lane = threadIdx.x & 31;
    if (wid >= T * WAY * C) return;
    int c   = wid % C;
    int way = (wid / C) % WAY;
    int t   = wid / (C * WAY);
    float v = 0.f;
    #pragma unroll
    for (int sh = 0; sh < SHOT; sh++) {
        const float* p = sf + ((size_t)((t * WAY + way) * SHOT + sh) * C + c) * HW;
        v += p[lane] + p[lane + 32] + p[lane + 64];
        if (lane < 4) v += p[lane + 96];
    }
    #pragma unroll
    for (int o = 16; o; o >>= 1) v += __shfl_xor_sync(~0u, v, o);
    if (!lane) ms[wid] = v * (1.0f / (SHOT * HW));
}

// ---------------- kernel 2: MERGED center_s + center_q + pads + zero (block-range dispatch) ----
#define CS_BLOCKS  (T * WS * (C/64))     // 1000
#define CQ_BLOCKS  (T * WQ * (C/64))     // 3000
#define NS_PAD     (T * WAY * (MS - SHOT*HW) * (C/2))   // 76800 half2
#define NQ_PAD     (T * (NPAD - NQ) * (C/2))            // 66560 half2
#define NSP_BLOCKS (NS_PAD / 256)        // 300
#define NQP_BLOCKS (NQ_PAD / 256)        // 260
#define CSZ_ELEMS  (T * WAY * NPAD / 4)  // 37760 float4
#define CSZ_BLOCKS ((CSZ_ELEMS + 255) / 256)  // 148
#define MERGED_BLOCKS (CS_BLOCKS + CQ_BLOCKS + NSP_BLOCKS + NQP_BLOCKS + CSZ_BLOCKS)

__global__ void __launch_bounds__(256) merged_prep_kernel(
        const float* __restrict__ sf, const float* __restrict__ qf,
        const float* __restrict__ ms,
        __half* __restrict__ S, __half* __restrict__ Q, float* __restrict__ cs) {
    __shared__ float tile[64 * 101];
    __shared__ float mean[64];
    int b = blockIdx.x;
    int tid = threadIdx.x;

    if (b < CS_BLOCKS) {
        // ---- center+transpose support ----
        int cc = b % (C / 64);
        int ws = (b / (C / 64)) % WS;
        int t  = b / ((C / 64) * WS);
        int way = ws / SHOT, sh = ws % SHOT;
        int c0 = cc * 64;
        const float* src = sf + ((size_t)(t * WS + ws) * C + c0) * HW;
        #pragma unroll
        for (int i = 0; i < 25; i++) {
            int idx = tid + i * 256;
            tile[(idx / 100) * 101 + (idx % 100)] = src[idx];
        }
        __syncthreads();
        const float* mrow = ms + (t * WAY + way) * C + c0;
        __half2* dst = (__half2*)(S + ((size_t)t * MTOT + way * MS + sh * HW) * C + c0);
        for (int i = tid; i < 32 * HW; i += 256) {
            int n = i / 32, cp = i % 32;
            float v0 = tile[(cp * 2) * 101 + n] - mrow[cp * 2];
            float v1 = tile[(cp * 2 + 1) * 101 + n] - mrow[cp * 2 + 1];
            dst[(size_t)n * (C / 2) + cp] = __floats2half2_rn(v0, v1);
        }
    } else if (b < CS_BLOCKS + CQ_BLOCKS) {
        // ---- center(fused mean)+transpose query ----
        int bb = b - CS_BLOCKS;
        int cc = bb % (C / 64);
        int q  = (bb / (C / 64)) % WQ;
        int t  = bb / ((C / 64) * WQ);
        int c0 = cc * 64;
        const float* src = qf + ((size_t)(t * WQ + q) * C + c0) * HW;
        int warp = tid >> 5, lane = tid & 31;
        #pragma unroll
        for (int i = 0; i < 25; i++) {
            int idx = tid + i * 256;
            tile[(idx / 100) * 101 + (idx % 100)] = src[idx];
        }
        __syncthreads();
        #pragma unroll
        for (int r = warp; r < 64; r += 8) {
            const float* row = &tile[r * 101];
            float v = row[lane] + row[lane + 32] + row[lane + 64];
            if (lane < 4) v += row[lane + 96];
            #pragma unroll
            for (int o = 16; o; o >>= 1) v += __shfl_xor_sync(~0u, v, o);
            if (!lane) mean[r] = v * (1.0f / HW);
        }
        __syncthreads();
        __half2* dst = (__half2*)(Q + ((size_t)t * NPAD + q * HW) * C + c0);
        for (int i = tid; i < 32 * HW; i += 256) {
            int n = i / 32, cp = i % 32;
            float v0 = tile[(cp * 2) * 101 + n] - mean[cp * 2];
            float v1 = tile[(cp * 2 + 1) * 101 + n] - mean[cp * 2 + 1];
            dst[(size_t)n * (C / 2) + cp] = __floats2half2_rn(v0, v1);
        }
    } else if (b < CS_BLOCKS + CQ_BLOCKS + NSP_BLOCKS) {
        // ---- zero S padding rows ----
        int i = (b - CS_BLOCKS - CQ_BLOCKS) * 256 + tid;
        int cp = i % (C / 2);
        int r  = (i / (C / 2)) % (MS - SHOT * HW);
        int wy = (i / ((C / 2) * (MS - SHOT * HW))) % WAY;
        int t  = i / ((C / 2) * (MS - SHOT * HW) * WAY);
        ((__half2*)S)[((size_t)t * MTOT + wy * MS + SHOT * HW + r) * (C / 2) + cp] =
            __floats2half2_rn(0.f, 0.f);
    } else if (b < CS_BLOCKS + CQ_BLOCKS + NSP_BLOCKS + NQP_BLOCKS) {
        // ---- zero Q padding rows ----
        int i = (b - CS_BLOCKS - CQ_BLOCKS - NSP_BLOCKS) * 256 + tid;
        int cp = i % (C / 2);
        int r  = (i / (C / 2)) % (NPAD - NQ);
        int t  = i / ((C / 2) * (NPAD - NQ));
        ((__half2*)Q)[((size_t)t * NPAD + NQ + r) * (C / 2) + cp] =
            __floats2half2_rn(0.f, 0.f);
    } else {
        // ---- zero colsum ----
        int i = (b - CS_BLOCKS - CQ_BLOCKS - NSP_BLOCKS - NQP_BLOCKS) * 256 + tid;
        if (i < CSZ_ELEMS)
            ((float4*)cs)[i] = make_float4(0.f, 0.f, 0.f, 0.f);
    }
}

// ---------------- kernel 3: fp16 HMMA GEMM (128x128) + fused column sum-of-squares ----------------
// R7 config: 128 threads (4 warps 2x2), warp tile 64x64, 2 CTAs/SM, 3 stages.
__global__ void __launch_bounds__(128, 2) gemm_hmma_kernel(const __half* __restrict__ A,
                                                           const __half* __restrict__ B,
                                                           float* __restrict__ colsum) {
    extern __shared__ char smem[];
    const uint32_t sb = smem_u32(smem);

    const int tid  = threadIdx.x;
    const int warp = tid >> 5, lane = tid & 31;
    const int wm = warp & 1;          // 0..1 : 64-row half (M)
    const int wn = warp >> 1;         // 0..1 : 64-col half (N)
    const int gid = lane >> 2, tig = lane & 3;

    const int t  = blockIdx.z;
    const int m0 = blockIdx.y * BM;
    const int n0 = blockIdx.x * BN;
    const __half* Ap = A + ((size_t)t * MTOT + m0) * C;
    const __half* Bp = B + ((size_t)t * NPAD + n0) * C;

    const int arow = lane & 15;
    const int akof = (lane >> 4) * 16;
    const int brow = ((lane >> 4) << 3) | (lane & 7);
    const int bkof = ((lane >> 3) & 1) * 16;

    auto issue = [&](int kc) {
        const int s  = kc % STAGES;
        const int k0 = kc * BKH;
        const uint32_t sA = sb + s * STAGE_BYTES;
        const uint32_t sB = sA + A_BYTES;
        #pragma unroll
        for (int it = 0; it < 8; it++) {               // A: 1024 x 16B
            int i   = tid + it * 128;
            int row = i >> 3, ch = i & 7;
            uint32_t dst = sA + SWZ(row * 128 + ch * 16);
            const __half* src = Ap + (size_t)row * C + k0 + ch * 8;
            asm volatile("cp.async.cg.shared.global [%0], [%1], 16;" :: "r"(dst), "l"(src));
        }
        #pragma unroll
        for (int it = 0; it < 8; it++) {               // B: 1024 x 16B
            int i   = tid + it * 128;
            int row = i >> 3, ch = i & 7;
            uint32_t dst = sB + SWZ(row * 128 + ch * 16);
            const __half* src = Bp + (size_t)row * C + k0 + ch * 8;
            asm volatile("cp.async.cg.shared.global [%0], [%1], 16;" :: "r"(dst), "l"(src));
        }
        asm volatile("cp.async.commit_group;");
    };

    float acc[4][8][4];
    #pragma unroll
    for (int mi = 0; mi < 4; mi++)
        #pragma unroll
        for (int ni = 0; ni < 8; ni++)
            #pragma unroll
            for (int r = 0; r < 4; r++) acc[mi][ni][r] = 0.f;

    issue(0); issue(1);

    for (int kc = 0; kc < KT; kc++) {
        if (kc < KT - 1) { WAITG(1); }   // stage kc complete (1 newer group may pend)
        else             { WAITG(0); }
        __syncthreads();                 // data visible + all warps done reading stage (kc-1)%3
        if (kc + 2 < KT) issue(kc + 2);  // writes stage (kc-1)%3 — safe after the sync

        const uint32_t sA = sb + (kc % STAGES) * STAGE_BYTES;
        const uint32_t sB = sA + A_BYTES;

        #pragma unroll
        for (int ks = 0; ks < 4; ks++) {
            const int kb = ks * 32;
            uint32_t a[4][4], b[8][2];
            #pragma unroll
            for (int mi = 0; mi < 4; mi++) {
                uint32_t addr = sA + SWZ((wm * 64 + mi * 16 + arow) * 128 + kb + akof);
                asm volatile("ldmatrix.sync.aligned.m8n8.x4.shared.b16 {%0,%1,%2,%3}, [%4];"
                             : "=r"(a[mi][0]), "=r"(a[mi][1]), "=r"(a[mi][2]), "=r"(a[mi][3])
                             : "r"(addr));
            }
            #pragma unroll
            for (int nj = 0; nj < 4; nj++) {
                uint32_t addr = sB + SWZ((wn * 64 + nj * 16 + brow) * 128 + kb + bkof);
                asm volatile("ldmatrix.sync.aligned.m8n8.x4.shared.b16 {%0,%1,%2,%3}, [%4];"
                             : "=r"(b[nj*2][0]), "=r"(b[nj*2][1]),
                               "=r"(b[nj*2+1][0]), "=r"(b[nj*2+1][1])
                             : "r"(addr));
            }
            #pragma unroll
            for (int mi = 0; mi < 4; mi++)
                #pragma unroll
                for (int ni = 0; ni < 8; ni++) {
                    asm volatile(
                        "mma.sync.aligned.m16n8k16.row.col.f32.f16.f16.f32 "
                        "{%0,%1,%2,%3}, {%4,%5,%6,%7}, {%8,%9}, {%0,%1,%2,%3};"
                        : "+f"(acc[mi][ni][0]), "+f"(acc[mi][ni][1]),
                          "+f"(acc[mi][ni][2]), "+f"(acc[mi][ni][3])
                        : "r"(a[mi][0]), "r"(a[mi][1]), "r"(a[mi][2]), "r"(a[mi][3]),
                          "r"(b[ni][0]), "r"(b[ni][1]));
                }
        }
    }

    // -------- fused epilogue: column sum of squares over this CTA's 128 rows --------
    const int way = m0 / MS;
    float* cs = colsum + ((size_t)t * WAY + way) * NPAD + n0;
    #pragma unroll
    for (int ni = 0; ni < 8; ni++) {
        float v0 = 0.f, v1 = 0.f;
        #pragma unroll
        for (int mi = 0; mi < 4; mi++) {
            v0 += acc[mi][ni][0] * acc[mi][ni][0] + acc[mi][ni][2] * acc[mi][ni][2];
            v1 += acc[mi][ni][1] * acc[mi][ni][1] + acc[mi][ni][3] * acc[mi][ni][3];
        }
        #pragma unroll
        for (int o = 4; o < 32; o <<= 1) {
            v0 += __shfl_xor_sync(~0u, v0, o);
            v1 += __shfl_xor_sync(~0u, v1, o);
        }
        if (gid == 0) {
            int col = wn * 64 + ni * 8 + tig * 2;
            atomicAdd(&cs[col], v0);
            atomicAdd(&cs[col + 1], v1);
        }
    }
}

// ---------------- kernel 4: /99, LeakyReLU(0.2), conv1d(k=stride=100), +bias ----------------
__global__ void final_kernel(const float* __restrict__ colsum, const float* __restrict__ cw,
                             const float* __restrict__ cb, float* __restrict__ out) {
    int wid  = (blockIdx.x * blockDim.x + threadIdx.x) >> 5;
    int lane = threadIdx.x & 31;
    if (wid >= T * WQ * WAY) return;
    int w = wid % WAY;
    int q = (wid / WAY) % WQ;
    int t = wid / (WAY * WQ);
    const float* cs = colsum + ((size_t)t * WAY + w) * NPAD + q * HW;
    float v = 0.f;
    #pragma unroll
    for (int i = 0; i < 4; i++) {
        int n = lane + 32 * i;
        if (n < HW) {
            float x = cs[n] * (1.0f / 99.0f);
            x = (x >= 0.f) ? x : 0.2f * x;
            v += x * cw[n];
        }
    }
    #pragma unroll
    for (int o = 16; o; o >>= 1) v += __shfl_xor_sync(~0u, v, o);
    if (!lane) out[wid] = v + cb[0];
}

// ---------------- launch ----------------
extern "C" void kernel_launch(void* const* d_in, const int* in_sizes, int n_in,
                              void* d_out, int out_size) {
    const float* qf = (const float*)d_in[0];
    const float* sf = (const float*)d_in[1];
    const float* cw = (const float*)d_in[2];
    const float* cb = (const float*)d_in[3];
    float* out = (float*)d_out;

    __half *dS, *dQ;
    float *dMS, *dCS;
    cudaGetSymbolAddress((void**)&dS,  g_S16);
    cudaGetSymbolAddress((void**)&dQ,  g_Q16);
    cudaGetSymbolAddress((void**)&dMS, g_meanS);
    cudaGetSymbolAddress((void**)&dCS, g_colsum);

    // 1) support means (small; must precede S-centering)
    {
        int warps = T * WAY * C;
        means_s_kernel<<<(warps * 32 + 255) / 256, 256>>>(sf, dMS);
    }
    // 2) merged: center_s + center_q + pads + zero colsum
    merged_prep_kernel<<<MERGED_BLOCKS, 256>>>(sf, qf, dMS, dS, dQ, dCS);
    // 3) GEMM + fused sum-of-squares (tail-friendly grid: 4720 = 15*296 + 280)
    cudaFuncSetAttribute(gemm_hmma_kernel, cudaFuncAttributeMaxDynamicSharedMemorySize, SMEM_TOTAL);
    dim3 grid(NPAD / BN, MTOT / BM, T);   // (59, 20, 4)
    gemm_hmma_kernel<<<grid, 128, SMEM_TOTAL>>>(dS, dQ, dCS);
    // 4) final score
    int warps = T * WQ * WAY;
    final_kernel<<<(warps * 32 + 255) / 256, 256>>>(dCS, cw, cb, out);
}